// round 3
// baseline (speedup 1.0000x reference)
#include <cuda_runtime.h>
#include <math.h>

// GradientHistLoss — single persistent kernel, 148 blocks x 1024 threads.
// No global atomics for histograms (per-block slots, fully overwritten each
// call -> no init kernel needed). 4 grid syncs total.
//
// Phases:
//  1. per-block top-11-bit histogram of gt -> g_histb[bx]
//  2. blocks 0..3: sum slots, locate bins/rems for ranks k, k+1
//  3. all blocks: collect candidate keys (bins b0/b1) into per-block buffers
//  4. (block-local, fused with 5) redundant 2-level radix select -> quantile
//  5. triangular soft histograms of pred+gt -> g_softb[bx]
//  6. block 0: finalize weighted L1 -> out

#define NBINS    64
#define BATCH    4
#define NBLOCKS  148
#define NTHREADS 1024
#define SBLKS    (NBLOCKS / BATCH)   // 37 blocks per sample
#define RB0      2048                // top 11 bits
#define RBMID    2048                // mid 11 bits
#define RBLO     1024                // low 10 bits
#define CAP      8192                // max candidates per block (= its elem share)

// ---- device scratch (static; fully overwritten each call) ----
__device__ unsigned g_histb[NBLOCKS][RB0];
__device__ unsigned g_bininfo[BATCH][4];      // b0, rem0, b1, rem1
__device__ unsigned g_cand[NBLOCKS][CAP];
__device__ unsigned g_ccnt[NBLOCKS];
__device__ float    g_softb[NBLOCKS][2 * NBINS];
__device__ unsigned          g_bar_count;
__device__ volatile unsigned g_bar_gen;

// -------------------------------------------------------------------------
__device__ __forceinline__ void grid_sync() {
    __syncthreads();
    if (threadIdx.x == 0) {
        __threadfence();
        unsigned gen = g_bar_gen;
        if (atomicAdd(&g_bar_count, 1u) == NBLOCKS - 1) {
            g_bar_count = 0u;
            __threadfence();
            g_bar_gen = gen + 1u;
        } else {
            while (g_bar_gen == gen) { __nanosleep(64); }
        }
        __threadfence();
    }
    __syncthreads();
}

// Block-collective: locate ranks r0, r1 in cnt[0..bins). Results in s_loc:
// {bin0, rem0, bin1, rem1}. Pass r1=0xFFFFFFFF to skip rank 1.
__device__ void locate2(const unsigned* cnt, int bins, unsigned r0, unsigned r1,
                        unsigned* s_scan, unsigned* s_loc) {
    int tid = threadIdx.x;
    int per = bins / NTHREADS;            // 2 or 1
    unsigned base = tid * per, sum = 0u;
    #pragma unroll
    for (int i = 0; i < 2; i++) if (i < per) sum += cnt[base + i];
    s_scan[tid] = sum;
    __syncthreads();
    for (int o = 1; o < NTHREADS; o <<= 1) {   // inclusive Hillis-Steele
        unsigned t = (tid >= o) ? s_scan[tid - o] : 0u;
        __syncthreads();
        s_scan[tid] += t;
        __syncthreads();
    }
    unsigned incl = s_scan[tid], excl = incl - sum;
    unsigned rs[2] = {r0, r1};
    #pragma unroll
    for (int j = 0; j < 2; j++) {
        unsigned r = rs[j];
        if (excl <= r && r < incl) {
            unsigned local = r - excl;
            unsigned d = base;
            for (;;) { unsigned c = cnt[d]; if (local < c) break; local -= c; d++; }
            s_loc[2 * j]     = d;
            s_loc[2 * j + 1] = local;
        }
    }
    __syncthreads();
}

// -------------------------------------------------------------------------
__global__ void __launch_bounds__(NTHREADS, 1)
ghl_kernel(const float* __restrict__ pred, const float* __restrict__ gt,
           int nper, unsigned k, float frac, float* __restrict__ out) {
    __shared__ unsigned sh[RB0];          // 8KB: hist buffers (reused as float)
    __shared__ unsigned s_scan[NTHREADS]; // 4KB
    __shared__ unsigned s_loc[4];
    __shared__ unsigned s_ccnt[SBLKS];
    __shared__ unsigned s_cnt;
    __shared__ float    s_red[BATCH];

    int tid  = threadIdx.x;
    int bx   = blockIdx.x;
    int samp = bx & 3;
    int sblk = bx >> 2;
    const float* gb = gt + (size_t)samp * nper;
    int nq = nper >> 2;                   // float4 count

    // ---- phase 1: per-block top-11-bit histogram of gt ----
    for (int i = tid; i < RB0; i += NTHREADS) sh[i] = 0u;
    __syncthreads();
    {
        const float4* g4 = (const float4*)gb;
        for (int i = sblk * NTHREADS + tid; i < nq; i += SBLKS * NTHREADS) {
            float4 v = g4[i];
            atomicAdd(&sh[__float_as_uint(v.x) >> 21], 1u);
            atomicAdd(&sh[__float_as_uint(v.y) >> 21], 1u);
            atomicAdd(&sh[__float_as_uint(v.z) >> 21], 1u);
            atomicAdd(&sh[__float_as_uint(v.w) >> 21], 1u);
        }
        for (int i = (nq << 2) + sblk * NTHREADS + tid; i < nper;
             i += SBLKS * NTHREADS)
            atomicAdd(&sh[__float_as_uint(gb[i]) >> 21], 1u);
    }
    __syncthreads();
    {   // vectorized slot store
        uint4* dst = (uint4*)g_histb[bx];
        const uint4* src = (const uint4*)sh;
        for (int i = tid; i < RB0 / 4; i += NTHREADS) dst[i] = src[i];
    }
    grid_sync();

    // ---- phase 2: blocks 0..3 sum slots + locate ranks k, k+1 ----
    if (bx < BATCH) {
        for (int i = tid; i < RB0; i += NTHREADS) {
            unsigned s = 0u;
            #pragma unroll 4
            for (int j = 0; j < SBLKS; j++) s += g_histb[4 * j + bx][i];
            sh[i] = s;
        }
        __syncthreads();
        locate2(sh, RB0, k, k + 1u, s_scan, s_loc);
        if (tid == 0) {
            g_bininfo[bx][0] = s_loc[0]; g_bininfo[bx][1] = s_loc[1];
            g_bininfo[bx][2] = s_loc[2]; g_bininfo[bx][3] = s_loc[3];
        }
    }
    grid_sync();

    // ---- phase 3: collect candidates of bins {b0, b1} into own slot ----
    unsigned b0 = g_bininfo[samp][0], rem0 = g_bininfo[samp][1];
    unsigned b1 = g_bininfo[samp][2], rem1 = g_bininfo[samp][3];
    if (tid == 0) s_cnt = 0u;
    __syncthreads();
    {
        const float4* g4 = (const float4*)gb;
        for (int i = sblk * NTHREADS + tid; i < nq; i += SBLKS * NTHREADS) {
            float4 v = g4[i];
            unsigned kk[4] = {__float_as_uint(v.x), __float_as_uint(v.y),
                              __float_as_uint(v.z), __float_as_uint(v.w)};
            #pragma unroll
            for (int c = 0; c < 4; c++) {
                unsigned t = kk[c] >> 21;
                if (t == b0 || t == b1)
                    g_cand[bx][atomicAdd(&s_cnt, 1u)] = kk[c];
            }
        }
        for (int i = (nq << 2) + sblk * NTHREADS + tid; i < nper;
             i += SBLKS * NTHREADS) {
            unsigned kk = __float_as_uint(gb[i]);
            unsigned t = kk >> 21;
            if (t == b0 || t == b1)
                g_cand[bx][atomicAdd(&s_cnt, 1u)] = kk;
        }
    }
    __syncthreads();
    if (tid == 0) g_ccnt[bx] = s_cnt;
    grid_sync();

    // ---- phase 4: redundant per-block 2-level select over candidates ----
    float invbw;
    {
        if (tid < SBLKS) s_ccnt[tid] = g_ccnt[4 * tid + samp];
        __syncthreads();
        unsigned topb[2] = {b0, b1};
        unsigned remr[2] = {rem0, rem1};
        float vals[2];
        #pragma unroll
        for (int r = 0; r < 2; r++) {
            // level A: mid 11 bits among keys with top bits == topb[r]
            for (int i = tid; i < RBMID; i += NTHREADS) sh[i] = 0u;
            __syncthreads();
            for (int s = 0; s < SBLKS; s++) {
                unsigned c = s_ccnt[s];
                const unsigned* buf = g_cand[4 * s + samp];
                for (unsigned i = tid; i < c; i += NTHREADS) {
                    unsigned kk = buf[i];
                    if ((kk >> 21) == topb[r])
                        atomicAdd(&sh[(kk >> 10) & 0x7FFu], 1u);
                }
            }
            __syncthreads();
            locate2(sh, RBMID, remr[r], 0xFFFFFFFFu, s_scan, s_loc);
            unsigned sa = s_loc[0], ra = s_loc[1];
            __syncthreads();
            // level B: low 10 bits
            for (int i = tid; i < RBLO; i += NTHREADS) sh[i] = 0u;
            __syncthreads();
            for (int s = 0; s < SBLKS; s++) {
                unsigned c = s_ccnt[s];
                const unsigned* buf = g_cand[4 * s + samp];
                for (unsigned i = tid; i < c; i += NTHREADS) {
                    unsigned kk = buf[i];
                    if ((kk >> 21) == topb[r] && ((kk >> 10) & 0x7FFu) == sa)
                        atomicAdd(&sh[kk & 0x3FFu], 1u);
                }
            }
            __syncthreads();
            locate2(sh, RBLO, ra, 0xFFFFFFFFu, s_scan, s_loc);
            unsigned sb = s_loc[0];
            vals[r] = __uint_as_float((topb[r] << 21) | (sa << 10) | sb);
            __syncthreads();
        }
        float mv = vals[0] + frac * (vals[1] - vals[0]);
        invbw = (mv > 0.0f) ? (float)NBINS / mv : 0.0f;
    }

    // ---- phase 5: triangular soft histograms (pred + gt), per-block slot ----
    {
        float* shf = (float*)sh;
        for (int i = tid; i < 2 * NBINS; i += NTHREADS) shf[i] = 0.0f;
        __syncthreads();
        const float4* p4 = (const float4*)(pred + (size_t)samp * nper);
        const float4* g4 = (const float4*)gb;
        for (int i = sblk * NTHREADS + tid; i < nq; i += SBLKS * NTHREADS) {
            float4 pv = p4[i];
            float4 gv = g4[i];
            float pe[4] = {pv.x, pv.y, pv.z, pv.w};
            float ge[4] = {gv.x, gv.y, gv.z, gv.w};
            #pragma unroll
            for (int c = 0; c < 4; c++) {
                float up = pe[c] * invbw;
                int   jp = (int)floorf(up);
                float fp = up - (float)jp;
                if (jp >= 0 && jp < NBINS) {
                    atomicAdd(&shf[jp], 1.0f - fp);
                    if (jp + 1 < NBINS) atomicAdd(&shf[jp + 1], fp);
                }
                float ug = ge[c] * invbw;
                int   jg = (int)floorf(ug);
                float fg = ug - (float)jg;
                if (jg >= 0 && jg < NBINS) {
                    atomicAdd(&shf[NBINS + jg], 1.0f - fg);
                    if (jg + 1 < NBINS) atomicAdd(&shf[NBINS + jg + 1], fg);
                }
            }
        }
        const float* pb = pred + (size_t)samp * nper;
        for (int i = (nq << 2) + sblk * NTHREADS + tid; i < nper;
             i += SBLKS * NTHREADS) {
            float up = pb[i] * invbw;
            int   jp = (int)floorf(up);
            float fp = up - (float)jp;
            if (jp >= 0 && jp < NBINS) {
                atomicAdd(&shf[jp], 1.0f - fp);
                if (jp + 1 < NBINS) atomicAdd(&shf[jp + 1], fp);
            }
            float ug = gb[i] * invbw;
            int   jg = (int)floorf(ug);
            float fg = ug - (float)jg;
            if (jg >= 0 && jg < NBINS) {
                atomicAdd(&shf[NBINS + jg], 1.0f - fg);
                if (jg + 1 < NBINS) atomicAdd(&shf[NBINS + jg + 1], fg);
            }
        }
        __syncthreads();
        for (int i = tid; i < 2 * NBINS; i += NTHREADS)
            g_softb[bx][i] = shf[i];
    }
    grid_sync();

    // ---- phase 6: finalize (block 0) ----
    if (bx == 0) {
        float* s_h = (float*)s_scan;      // 512 floats: [b][idx 0..127]
        if (tid < BATCH * 2 * NBINS) {
            int b = tid >> 7, idx = tid & 127;
            float s = 0.0f;
            #pragma unroll 4
            for (int j = 0; j < SBLKS; j++) s += g_softb[4 * j + b][idx];
            s_h[tid] = s;
        }
        __syncthreads();
        int warp = tid >> 5, lane = tid & 31;
        if (warp < BATCH) {
            int b = warp;
            float sp = s_h[b * 128 + lane] + s_h[b * 128 + 32 + lane];
            float sg = s_h[b * 128 + 64 + lane] + s_h[b * 128 + 96 + lane];
            #pragma unroll
            for (int o = 16; o >= 1; o >>= 1) {
                sp += __shfl_xor_sync(0xFFFFFFFFu, sp, o);
                sg += __shfl_xor_sync(0xFFFFFFFFu, sg, o);
            }
            float acc = 0.0f;
            #pragma unroll
            for (int h = 0; h < 2; h++) {
                int j = h * 32 + lane;
                float bw = expf(0.4f * (float)j / (float)NBINS);
                float p = s_h[b * 128 + j];
                float g = s_h[b * 128 + 64 + j];
                acc += fabsf(p / sp - g / sg) * bw;
            }
            #pragma unroll
            for (int o = 16; o >= 1; o >>= 1)
                acc += __shfl_xor_sync(0xFFFFFFFFu, acc, o);
            if (lane == 0) s_red[b] = acc * (1.0f / (float)NBINS);
        }
        __syncthreads();
        if (tid == 0)
            out[0] = (s_red[0] + s_red[1] + s_red[2] + s_red[3]) *
                     (1.0f / (float)BATCH);
    }
}

// -------------------------------------------------------------------------
extern "C" void kernel_launch(void* const* d_in, const int* in_sizes, int n_in,
                              void* d_out, int out_size) {
    const float* pred = (const float*)d_in[0];
    const float* gt   = (const float*)d_in[1];
    int ntot = in_sizes[0];
    int nper = ntot / BATCH;

    double pos = 0.95 * (double)(nper - 1);
    unsigned k = (unsigned)pos;
    float frac = (float)(pos - (double)k);

    ghl_kernel<<<NBLOCKS, NTHREADS>>>(pred, gt, nper, k, frac, (float*)d_out);
}

// round 4
// speedup vs baseline: 1.7459x; 1.7459x over previous
#include <cuda_runtime.h>
#include <math.h>

// GradientHistLoss — persistent kernel, 148x1024.
// Exact p95 via 3-level radix select (11+11+10 bits), each level done as
// per-block partial histograms (shared -> private global slot, NO global
// atomics), combined+located by 4 blocks. No candidate buffers, no
// redundant per-block selection work. 7 grid syncs.

#define NBINS    64
#define BATCH    4
#define NBLOCKS  148
#define NTHREADS 1024
#define SBLKS    37
#define RTOP     2048
#define RMID     2048
#define RLOW     1024
#define SKIP     0xFFFFFFFFu

// ---- device scratch (fully overwritten each call) ----
__device__ unsigned g_top[NBLOCKS][RTOP];
__device__ unsigned g_mid[NBLOCKS][2 * RMID];
__device__ unsigned g_low[NBLOCKS][2 * RLOW];
__device__ unsigned g_tinfo[BATCH][4];   // b0, rem0, b1, rem1
__device__ unsigned g_minfo[BATCH][4];   // m0, rm0, m1, rm1
__device__ float    g_invbw[BATCH];
__device__ float    g_softb[NBLOCKS][2 * NBINS];
__device__ unsigned          g_bar_count;
__device__ volatile unsigned g_bar_gen;

// -------------------------------------------------------------------------
__device__ __forceinline__ void grid_sync() {
    __syncthreads();
    if (threadIdx.x == 0) {
        __threadfence();
        unsigned gen = g_bar_gen;
        if (atomicAdd(&g_bar_count, 1u) == NBLOCKS - 1) {
            g_bar_count = 0u;
            __threadfence();
            g_bar_gen = gen + 1u;
        } else {
            while (g_bar_gen == gen) { __nanosleep(64); }
        }
        __threadfence();
    }
    __syncthreads();
}

// Block-collective: locate ranks r0 (and r1 unless SKIP) in cnt[0..bins).
// Results broadcast via s_loc = {bin0, rem0, bin1, rem1}.
__device__ void locate2(const unsigned* cnt, int bins, unsigned r0, unsigned r1,
                        unsigned* s_ws, unsigned* s_loc) {
    int tid = threadIdx.x, lane = tid & 31, warp = tid >> 5;
    int per = bins >> 10;                  // 1 or 2 (NTHREADS = 1024)
    unsigned base = tid * per, sum = 0u;
    #pragma unroll
    for (int i = 0; i < 2; i++) if (i < per) sum += cnt[base + i];
    // warp-inclusive scan
    unsigned incl = sum;
    #pragma unroll
    for (int o = 1; o < 32; o <<= 1) {
        unsigned v = __shfl_up_sync(0xFFFFFFFFu, incl, o);
        if (lane >= o) incl += v;
    }
    if (lane == 31) s_ws[warp] = incl;
    __syncthreads();
    if (warp == 0) {
        unsigned v = s_ws[lane];
        unsigned wi = v;
        #pragma unroll
        for (int o = 1; o < 32; o <<= 1) {
            unsigned t = __shfl_up_sync(0xFFFFFFFFu, wi, o);
            if (lane >= o) wi += t;
        }
        s_ws[lane] = wi - v;               // exclusive warp offsets
    }
    __syncthreads();
    unsigned inclT = incl + s_ws[warp];
    unsigned exclT = inclT - sum;
    #pragma unroll
    for (int j = 0; j < 2; j++) {
        unsigned r = (j == 0) ? r0 : r1;
        if (r != SKIP && exclT <= r && r < inclT) {
            unsigned local = r - exclT, d = base;
            while (local >= cnt[d]) { local -= cnt[d]; d++; }
            s_loc[2 * j] = d;
            s_loc[2 * j + 1] = local;
        }
    }
    __syncthreads();
}

// -------------------------------------------------------------------------
__global__ void __launch_bounds__(NTHREADS, 1)
ghl_kernel(const float* __restrict__ pred, const float* __restrict__ gt,
           int nper, unsigned k, float frac, float* __restrict__ out) {
    __shared__ unsigned sh[2 * RMID];      // 16KB, reused every phase
    __shared__ unsigned s_ws[32];
    __shared__ unsigned s_loc[4];
    __shared__ float    s_red[BATCH];

    int tid  = threadIdx.x;
    int bx   = blockIdx.x;
    int samp = bx & 3;
    int sblk = bx >> 2;
    const float*  gb = gt + (size_t)samp * nper;
    const float4* g4 = (const float4*)gb;
    int nq   = nper >> 2;
    int i0   = sblk * NTHREADS + tid;
    int istr = SBLKS * NTHREADS;
    int tail0 = (nq << 2) + i0;

    // ================= phase 1: per-block top-11-bit hist =================
    for (int i = tid; i < RTOP; i += NTHREADS) sh[i] = 0u;
    __syncthreads();
    for (int i = i0; i < nq; i += istr) {
        float4 v = g4[i];
        atomicAdd(&sh[__float_as_uint(v.x) >> 21], 1u);
        atomicAdd(&sh[__float_as_uint(v.y) >> 21], 1u);
        atomicAdd(&sh[__float_as_uint(v.z) >> 21], 1u);
        atomicAdd(&sh[__float_as_uint(v.w) >> 21], 1u);
    }
    for (int i = tail0; i < nper; i += istr)
        atomicAdd(&sh[__float_as_uint(gb[i]) >> 21], 1u);
    __syncthreads();
    {
        uint4* dst = (uint4*)g_top[bx];
        const uint4* src = (const uint4*)sh;
        for (int i = tid; i < RTOP / 4; i += NTHREADS) dst[i] = src[i];
    }
    grid_sync();

    // ================= phase 2: locate top bins (blocks 0..3) =============
    if (bx < BATCH) {
        for (int i = tid; i < RTOP; i += NTHREADS) {
            unsigned s = 0u;
            #pragma unroll 4
            for (int j = 0; j < SBLKS; j++) s += g_top[4 * j + bx][i];
            sh[i] = s;
        }
        __syncthreads();
        locate2(sh, RTOP, k, k + 1u, s_ws, s_loc);
        if (tid == 0) {
            g_tinfo[bx][0] = s_loc[0]; g_tinfo[bx][1] = s_loc[1];
            g_tinfo[bx][2] = s_loc[2]; g_tinfo[bx][3] = s_loc[3];
        }
    }
    grid_sync();

    // ================= phase 3: per-block mid-11-bit hists ================
    unsigned b0 = g_tinfo[samp][0], b1 = g_tinfo[samp][2];
    for (int i = tid; i < 2 * RMID; i += NTHREADS) sh[i] = 0u;
    __syncthreads();
    for (int i = i0; i < nq; i += istr) {
        float4 v = g4[i];
        unsigned kk[4] = {__float_as_uint(v.x), __float_as_uint(v.y),
                          __float_as_uint(v.z), __float_as_uint(v.w)};
        #pragma unroll
        for (int c = 0; c < 4; c++) {
            unsigned t = kk[c] >> 21, m = (kk[c] >> 10) & 0x7FFu;
            if (t == b0)      atomicAdd(&sh[m], 1u);
            else if (t == b1) atomicAdd(&sh[RMID + m], 1u);
        }
    }
    for (int i = tail0; i < nper; i += istr) {
        unsigned kk = __float_as_uint(gb[i]);
        unsigned t = kk >> 21, m = (kk >> 10) & 0x7FFu;
        if (t == b0)      atomicAdd(&sh[m], 1u);
        else if (t == b1) atomicAdd(&sh[RMID + m], 1u);
    }
    __syncthreads();
    {
        uint4* dst = (uint4*)g_mid[bx];
        const uint4* src = (const uint4*)sh;
        for (int i = tid; i < 2 * RMID / 4; i += NTHREADS) dst[i] = src[i];
    }
    grid_sync();

    // ================= phase 4: locate mid bins (blocks 0..3) =============
    if (bx < BATCH) {
        for (int i = tid; i < 2 * RMID; i += NTHREADS) {
            unsigned s = 0u;
            #pragma unroll 4
            for (int j = 0; j < SBLKS; j++) s += g_mid[4 * j + bx][i];
            sh[i] = s;
        }
        __syncthreads();
        unsigned B0 = g_tinfo[bx][0], R0 = g_tinfo[bx][1];
        unsigned B1 = g_tinfo[bx][2], R1 = g_tinfo[bx][3];
        int sm = (B0 == B1);
        locate2(sh, RMID, R0, sm ? R0 + 1u : SKIP, s_ws, s_loc);
        unsigned m0 = s_loc[0], rm0 = s_loc[1], m1, rm1;
        if (sm) { m1 = s_loc[2]; rm1 = s_loc[3]; }
        else {
            locate2(sh + RMID, RMID, R1, SKIP, s_ws, s_loc);
            m1 = s_loc[0]; rm1 = s_loc[1];
        }
        if (tid == 0) {
            g_minfo[bx][0] = m0; g_minfo[bx][1] = rm0;
            g_minfo[bx][2] = m1; g_minfo[bx][3] = rm1;
        }
    }
    grid_sync();

    // ================= phase 5: per-block low-10-bit hists ================
    {
        unsigned p0 = (b0 << 11) | g_minfo[samp][0];
        unsigned p1 = (b1 << 11) | g_minfo[samp][2];
        for (int i = tid; i < 2 * RLOW; i += NTHREADS) sh[i] = 0u;
        __syncthreads();
        for (int i = i0; i < nq; i += istr) {
            float4 v = g4[i];
            unsigned kk[4] = {__float_as_uint(v.x), __float_as_uint(v.y),
                              __float_as_uint(v.z), __float_as_uint(v.w)};
            #pragma unroll
            for (int c = 0; c < 4; c++) {
                unsigned pf = kk[c] >> 10, lo = kk[c] & 0x3FFu;
                if (pf == p0)      atomicAdd(&sh[lo], 1u);
                else if (pf == p1) atomicAdd(&sh[RLOW + lo], 1u);
            }
        }
        for (int i = tail0; i < nper; i += istr) {
            unsigned kk = __float_as_uint(gb[i]);
            unsigned pf = kk >> 10, lo = kk & 0x3FFu;
            if (pf == p0)      atomicAdd(&sh[lo], 1u);
            else if (pf == p1) atomicAdd(&sh[RLOW + lo], 1u);
        }
        __syncthreads();
        uint4* dst = (uint4*)g_low[bx];
        const uint4* src = (const uint4*)sh;
        for (int i = tid; i < 2 * RLOW / 4; i += NTHREADS) dst[i] = src[i];
    }
    grid_sync();

    // ================= phase 6: final select + invbw (blocks 0..3) ========
    if (bx < BATCH) {
        for (int i = tid; i < 2 * RLOW; i += NTHREADS) {
            unsigned s = 0u;
            #pragma unroll 4
            for (int j = 0; j < SBLKS; j++) s += g_low[4 * j + bx][i];
            sh[i] = s;
        }
        __syncthreads();
        unsigned B0 = g_tinfo[bx][0], B1 = g_tinfo[bx][2];
        unsigned M0 = g_minfo[bx][0], RM0 = g_minfo[bx][1];
        unsigned M1 = g_minfo[bx][2], RM1 = g_minfo[bx][3];
        unsigned P0 = (B0 << 11) | M0, P1 = (B1 << 11) | M1;
        int sm2 = (P0 == P1);
        locate2(sh, RLOW, RM0, sm2 ? RM0 + 1u : SKIP, s_ws, s_loc);
        unsigned d0 = s_loc[0], d1;
        if (sm2) d1 = s_loc[2];
        else {
            locate2(sh + RLOW, RLOW, RM1, SKIP, s_ws, s_loc);
            d1 = s_loc[0];
        }
        if (tid == 0) {
            float v0 = __uint_as_float((P0 << 10) | d0);
            float v1 = __uint_as_float((P1 << 10) | d1);
            float mv = v0 + frac * (v1 - v0);
            g_invbw[bx] = (mv > 0.0f) ? (float)NBINS / mv : 0.0f;
        }
    }
    grid_sync();

    // ================= phase 7: soft histograms (4 replicated copies) =====
    {
        float invbw = g_invbw[samp];
        float* shf = (float*)sh;
        for (int i = tid; i < 4 * 2 * NBINS; i += NTHREADS) shf[i] = 0.0f;
        __syncthreads();
        float* my = shf + ((tid >> 5) & 3) * 2 * NBINS;
        const float4* p4 = (const float4*)(pred + (size_t)samp * nper);
        for (int i = i0; i < nq; i += istr) {
            float4 pv = p4[i];
            float4 gv = g4[i];
            float pe[4] = {pv.x, pv.y, pv.z, pv.w};
            float ge[4] = {gv.x, gv.y, gv.z, gv.w};
            #pragma unroll
            for (int c = 0; c < 4; c++) {
                float up = pe[c] * invbw;
                int   jp = (int)floorf(up);
                float fp = up - (float)jp;
                if (jp >= 0 && jp < NBINS) {
                    atomicAdd(&my[jp], 1.0f - fp);
                    if (jp + 1 < NBINS) atomicAdd(&my[jp + 1], fp);
                }
                float ug = ge[c] * invbw;
                int   jg = (int)floorf(ug);
                float fg = ug - (float)jg;
                if (jg >= 0 && jg < NBINS) {
                    atomicAdd(&my[NBINS + jg], 1.0f - fg);
                    if (jg + 1 < NBINS) atomicAdd(&my[NBINS + jg + 1], fg);
                }
            }
        }
        const float* pb = pred + (size_t)samp * nper;
        for (int i = tail0; i < nper; i += istr) {
            float up = pb[i] * invbw;
            int   jp = (int)floorf(up);
            float fp = up - (float)jp;
            if (jp >= 0 && jp < NBINS) {
                atomicAdd(&my[jp], 1.0f - fp);
                if (jp + 1 < NBINS) atomicAdd(&my[jp + 1], fp);
            }
            float ug = gb[i] * invbw;
            int   jg = (int)floorf(ug);
            float fg = ug - (float)jg;
            if (jg >= 0 && jg < NBINS) {
                atomicAdd(&my[NBINS + jg], 1.0f - fg);
                if (jg + 1 < NBINS) atomicAdd(&my[NBINS + jg + 1], fg);
            }
        }
        __syncthreads();
        for (int i = tid; i < 2 * NBINS; i += NTHREADS)
            g_softb[bx][i] = shf[i] + shf[128 + i] + shf[256 + i] + shf[384 + i];
    }
    grid_sync();

    // ================= phase 8: finalize (block 0) ========================
    if (bx == 0) {
        float* s_h = (float*)sh;           // 512 floats: [b][0..127]
        if (tid < BATCH * 2 * NBINS) {
            int b = tid >> 7, idx = tid & 127;
            float s = 0.0f;
            #pragma unroll 4
            for (int j = 0; j < SBLKS; j++) s += g_softb[4 * j + b][idx];
            s_h[tid] = s;
        }
        __syncthreads();
        int warp = tid >> 5, lane = tid & 31;
        if (warp < BATCH) {
            int b = warp;
            float sp = s_h[b * 128 + lane] + s_h[b * 128 + 32 + lane];
            float sg = s_h[b * 128 + 64 + lane] + s_h[b * 128 + 96 + lane];
            #pragma unroll
            for (int o = 16; o >= 1; o >>= 1) {
                sp += __shfl_xor_sync(0xFFFFFFFFu, sp, o);
                sg += __shfl_xor_sync(0xFFFFFFFFu, sg, o);
            }
            float acc = 0.0f;
            #pragma unroll
            for (int h = 0; h < 2; h++) {
                int j = h * 32 + lane;
                float bw = expf(0.4f * (float)j / (float)NBINS);
                float p = s_h[b * 128 + j];
                float g = s_h[b * 128 + 64 + j];
                acc += fabsf(p / sp - g / sg) * bw;
            }
            #pragma unroll
            for (int o = 16; o >= 1; o >>= 1)
                acc += __shfl_xor_sync(0xFFFFFFFFu, acc, o);
            if (lane == 0) s_red[b] = acc * (1.0f / (float)NBINS);
        }
        __syncthreads();
        if (tid == 0)
            out[0] = (s_red[0] + s_red[1] + s_red[2] + s_red[3]) *
                     (1.0f / (float)BATCH);
    }
}

// -------------------------------------------------------------------------
extern "C" void kernel_launch(void* const* d_in, const int* in_sizes, int n_in,
                              void* d_out, int out_size) {
    const float* pred = (const float*)d_in[0];
    const float* gt   = (const float*)d_in[1];
    int ntot = in_sizes[0];
    int nper = ntot / BATCH;

    double pos = 0.95 * (double)(nper - 1);
    unsigned k = (unsigned)pos;
    float frac = (float)(pos - (double)k);

    ghl_kernel<<<NBLOCKS, NTHREADS>>>(pred, gt, nper, k, frac, (float*)d_out);
}